// round 1
// baseline (speedup 1.0000x reference)
#include <cuda_runtime.h>
#include <math.h>

#define BB 8
#define NN 1024
#define HH 12
#define DHD 64        // dim per head
#define DIM 768
#define DH  768       // H * DHD
#define E3  2304      // 3 * DH
#define NTOK (BB*NN)  // 8192

// Scratch (device globals; no runtime allocation allowed)
__device__ float g_q[BB*HH*NN*DHD];
__device__ float g_k[BB*HH*NN*DHD];
__device__ float g_v[BB*HH*NN*DHD];
__device__ float g_o[NTOK*DH];

// ---------------------------------------------------------------------------
// GEMM 1: qkv[m, e] = sum_k img[m, k] * W_qkv[e, k], scattered into g_q/g_k/g_v
// Tiles: 64x64 output per block, BK=16, 256 threads, 4x4 per thread.
// ---------------------------------------------------------------------------
__global__ __launch_bounds__(256) void qkv_gemm(const float* __restrict__ X,
                                                const float* __restrict__ W) {
    __shared__ float As[16][68];   // As[k][m]
    __shared__ float Bs[16][68];   // Bs[k][e]
    const int m0 = blockIdx.y * 64;
    const int n0 = blockIdx.x * 64;
    const int tid = threadIdx.x;
    const int tm = tid >> 4;       // 0..15
    const int tn = tid & 15;       // 0..15
    const int lr = tid >> 2;       // 0..63 (row for loads)
    const int lk = (tid & 3) * 4;  // k offset for loads

    float acc[4][4] = {};

    const float* xp = X + (size_t)(m0 + lr) * DIM + lk;
    const float* wp = W + (size_t)(n0 + lr) * DIM + lk;

    for (int k0 = 0; k0 < DIM; k0 += 16) {
        float4 av = *(const float4*)(xp + k0);
        float4 bv = *(const float4*)(wp + k0);
        As[lk + 0][lr] = av.x; As[lk + 1][lr] = av.y;
        As[lk + 2][lr] = av.z; As[lk + 3][lr] = av.w;
        Bs[lk + 0][lr] = bv.x; Bs[lk + 1][lr] = bv.y;
        Bs[lk + 2][lr] = bv.z; Bs[lk + 3][lr] = bv.w;
        __syncthreads();
        #pragma unroll
        for (int k = 0; k < 16; k++) {
            float4 a = *(const float4*)&As[k][tm * 4];
            float4 b = *(const float4*)&Bs[k][tn * 4];
            float af[4] = {a.x, a.y, a.z, a.w};
            float bf[4] = {b.x, b.y, b.z, b.w};
            #pragma unroll
            for (int i = 0; i < 4; i++)
                #pragma unroll
                for (int j = 0; j < 4; j++)
                    acc[i][j] = fmaf(af[i], bf[j], acc[i][j]);
        }
        __syncthreads();
    }

    // Scatter into g_q / g_k / g_v with layout [b, h, n, d]
    #pragma unroll
    for (int i = 0; i < 4; i++) {
        const int m = m0 + tm * 4 + i;
        const int b = m >> 10;
        const int ntok = m & 1023;
        #pragma unroll
        for (int j = 0; j < 4; j++) {
            const int e = n0 + tn * 4 + j;
            const int h = e / 192;
            const int r = e - h * 192;
            float* dst = (r < 64) ? g_q : (r < 128 ? g_k : g_v);
            const int rr = r & 63;
            dst[(((size_t)b * HH + h) * NN + ntok) * DHD + rr] = acc[i][j];
        }
    }
}

// ---------------------------------------------------------------------------
// Flash attention per (b*h, q-tile of 64). 256 threads; 4x4 register tiles.
//  S = (Q K^T) * 8 ; online softmax ; O += P V ; O /= l
// SMEM: Qs (d-major), Ks (d-major), Vs (row-major), Ps (row-major) + row stats
// ---------------------------------------------------------------------------
__global__ __launch_bounds__(256) void attn_kernel() {
    extern __shared__ float sm[];
    float* Qs = sm;                 // [64 d][64 r]
    float* Ks = Qs + 64 * 64;       // [64 d][64 c]
    float* Vs = Ks + 64 * 64;       // [64 c][64 d]
    float* Ps = Vs + 64 * 64;       // [64 r][64 c]
    float* m_row = Ps + 64 * 64;    // [64]
    float* l_row = m_row + 64;      // [64]

    const int bh = blockIdx.y;          // 0..95  (b*12 + h)
    const int q0 = blockIdx.x * 64;
    const int tid = threadIdx.x;
    const int tm = tid >> 4;            // 0..15
    const int tn = tid & 15;            // 0..15
    const int lr = tid >> 2;            // 0..63
    const int ld0 = (tid & 3) * 16;     // 0,16,32,48

    const float* Qg = g_q + ((size_t)bh * NN + q0) * DHD;
    const float* Kg = g_k + (size_t)bh * NN * DHD;
    const float* Vg = g_v + (size_t)bh * NN * DHD;

    // Load Q tile transposed (d-major)
    #pragma unroll
    for (int c4 = 0; c4 < 4; c4++) {
        float4 v = *(const float4*)(Qg + lr * DHD + ld0 + c4 * 4);
        Qs[(ld0 + c4 * 4 + 0) * 64 + lr] = v.x;
        Qs[(ld0 + c4 * 4 + 1) * 64 + lr] = v.y;
        Qs[(ld0 + c4 * 4 + 2) * 64 + lr] = v.z;
        Qs[(ld0 + c4 * 4 + 3) * 64 + lr] = v.w;
    }
    if (tid < 64) { m_row[tid] = -1e30f; l_row[tid] = 0.f; }

    float o_acc[4][4] = {};
    __syncthreads();

    for (int kt = 0; kt < 16; kt++) {
        const float* Kt = Kg + (size_t)kt * 64 * DHD;
        const float* Vt = Vg + (size_t)kt * 64 * DHD;
        // Load K transposed (d-major), V row-major
        #pragma unroll
        for (int c4 = 0; c4 < 4; c4++) {
            float4 kv = *(const float4*)(Kt + lr * DHD + ld0 + c4 * 4);
            Ks[(ld0 + c4 * 4 + 0) * 64 + lr] = kv.x;
            Ks[(ld0 + c4 * 4 + 1) * 64 + lr] = kv.y;
            Ks[(ld0 + c4 * 4 + 2) * 64 + lr] = kv.z;
            Ks[(ld0 + c4 * 4 + 3) * 64 + lr] = kv.w;
            float4 vv = *(const float4*)(Vt + lr * DHD + ld0 + c4 * 4);
            *(float4*)&Vs[lr * 64 + ld0 + c4 * 4] = vv;
        }
        __syncthreads();

        // S = Q K^T (4x4 per thread)
        float s[4][4] = {};
        #pragma unroll 8
        for (int d = 0; d < 64; d++) {
            float4 a = *(const float4*)&Qs[d * 64 + tm * 4];
            float4 b = *(const float4*)&Ks[d * 64 + tn * 4];
            float af[4] = {a.x, a.y, a.z, a.w};
            float bf[4] = {b.x, b.y, b.z, b.w};
            #pragma unroll
            for (int i = 0; i < 4; i++)
                #pragma unroll
                for (int j = 0; j < 4; j++)
                    s[i][j] = fmaf(af[i], bf[j], s[i][j]);
        }
        // scale (NOTE: reference MULTIPLIES by sqrt(dh)=8)
        #pragma unroll
        for (int i = 0; i < 4; i++)
            #pragma unroll
            for (int j = 0; j < 4; j++)
                s[i][j] *= 8.0f;

        // Online softmax per row (rows owned by one warp: 16 lanes / row)
        float m_old[4];
        #pragma unroll
        for (int i = 0; i < 4; i++) m_old[i] = m_row[tm * 4 + i];
        __syncwarp();

        float f[4];
        #pragma unroll
        for (int i = 0; i < 4; i++) {
            float mt = fmaxf(fmaxf(s[i][0], s[i][1]), fmaxf(s[i][2], s[i][3]));
            #pragma unroll
            for (int off = 1; off < 16; off <<= 1)
                mt = fmaxf(mt, __shfl_xor_sync(0xffffffffu, mt, off));
            const float mn = fmaxf(m_old[i], mt);
            float ls = 0.f;
            #pragma unroll
            for (int j = 0; j < 4; j++) {
                s[i][j] = __expf(s[i][j] - mn);
                ls += s[i][j];
            }
            #pragma unroll
            for (int off = 1; off < 16; off <<= 1)
                ls += __shfl_xor_sync(0xffffffffu, ls, off);
            f[i] = __expf(m_old[i] - mn);
            if (tn == 0) {
                m_row[tm * 4 + i] = mn;
                l_row[tm * 4 + i] = l_row[tm * 4 + i] * f[i] + ls;
            }
            // store P row (float4, conflict-free)
            *(float4*)&Ps[(tm * 4 + i) * 64 + tn * 4] =
                make_float4(s[i][0], s[i][1], s[i][2], s[i][3]);
        }
        __syncthreads();

        // Rescale accumulator and O += P V
        #pragma unroll
        for (int i = 0; i < 4; i++)
            #pragma unroll
            for (int j = 0; j < 4; j++)
                o_acc[i][j] *= f[i];

        #pragma unroll 8
        for (int c = 0; c < 64; c++) {
            float4 b = *(const float4*)&Vs[c * 64 + tn * 4];
            float bf[4] = {b.x, b.y, b.z, b.w};
            float a0 = Ps[(tm * 4 + 0) * 64 + c];
            float a1 = Ps[(tm * 4 + 1) * 64 + c];
            float a2 = Ps[(tm * 4 + 2) * 64 + c];
            float a3 = Ps[(tm * 4 + 3) * 64 + c];
            #pragma unroll
            for (int j = 0; j < 4; j++) {
                o_acc[0][j] = fmaf(a0, bf[j], o_acc[0][j]);
                o_acc[1][j] = fmaf(a1, bf[j], o_acc[1][j]);
                o_acc[2][j] = fmaf(a2, bf[j], o_acc[2][j]);
                o_acc[3][j] = fmaf(a3, bf[j], o_acc[3][j]);
            }
        }
        __syncthreads();
    }

    // Epilogue: divide by l, write merged-heads layout [b, n, h*64 + d]
    const int b = bh / HH;
    const int h = bh - b * HH;
    #pragma unroll
    for (int i = 0; i < 4; i++) {
        const int r = tm * 4 + i;
        const float il = 1.0f / l_row[r];
        float4 o = make_float4(o_acc[i][0] * il, o_acc[i][1] * il,
                               o_acc[i][2] * il, o_acc[i][3] * il);
        size_t idx = ((size_t)b * NN + q0 + r) * DH + h * DHD + tn * 4;
        *(float4*)&g_o[idx] = o;
    }
}

// ---------------------------------------------------------------------------
// GEMM 3: out[m, d] = sum_e g_o[m, e] * W_fc[d, e] + b_fc[d]
// ---------------------------------------------------------------------------
__global__ __launch_bounds__(256) void out_gemm(const float* __restrict__ Wfc,
                                                const float* __restrict__ bfc,
                                                float* __restrict__ out) {
    __shared__ float As[16][68];
    __shared__ float Bs[16][68];
    const int m0 = blockIdx.y * 64;
    const int n0 = blockIdx.x * 64;
    const int tid = threadIdx.x;
    const int tm = tid >> 4;
    const int tn = tid & 15;
    const int lr = tid >> 2;
    const int lk = (tid & 3) * 4;

    float acc[4][4] = {};

    const float* xp = g_o + (size_t)(m0 + lr) * DH + lk;
    const float* wp = Wfc + (size_t)(n0 + lr) * DH + lk;

    for (int k0 = 0; k0 < DH; k0 += 16) {
        float4 av = *(const float4*)(xp + k0);
        float4 bv = *(const float4*)(wp + k0);
        As[lk + 0][lr] = av.x; As[lk + 1][lr] = av.y;
        As[lk + 2][lr] = av.z; As[lk + 3][lr] = av.w;
        Bs[lk + 0][lr] = bv.x; Bs[lk + 1][lr] = bv.y;
        Bs[lk + 2][lr] = bv.z; Bs[lk + 3][lr] = bv.w;
        __syncthreads();
        #pragma unroll
        for (int k = 0; k < 16; k++) {
            float4 a = *(const float4*)&As[k][tm * 4];
            float4 b = *(const float4*)&Bs[k][tn * 4];
            float af[4] = {a.x, a.y, a.z, a.w};
            float bf[4] = {b.x, b.y, b.z, b.w};
            #pragma unroll
            for (int i = 0; i < 4; i++)
                #pragma unroll
                for (int j = 0; j < 4; j++)
                    acc[i][j] = fmaf(af[i], bf[j], acc[i][j]);
        }
        __syncthreads();
    }

    #pragma unroll
    for (int i = 0; i < 4; i++) {
        const int m = m0 + tm * 4 + i;
        #pragma unroll
        for (int j = 0; j < 4; j++) {
            const int n = n0 + tn * 4 + j;
            out[(size_t)m * DIM + n] = acc[i][j] + bfc[n];
        }
    }
}

// ---------------------------------------------------------------------------
extern "C" void kernel_launch(void* const* d_in, const int* in_sizes, int n_in,
                              void* d_out, int out_size) {
    const float* img  = (const float*)d_in[0];   // [8,1024,768]
    const float* Wqkv = (const float*)d_in[1];   // [2304,768]
    const float* Wfc  = (const float*)d_in[2];   // [768,768]
    const float* bfc  = (const float*)d_in[3];   // [768]
    float* out = (float*)d_out;                  // [8,1024,768]

    // 1) QKV projection + scatter
    qkv_gemm<<<dim3(E3 / 64, NTOK / 64), 256>>>(img, Wqkv);

    // 2) Flash attention (66 KB dynamic SMEM)
    const int smem = (4 * 64 * 64 + 128) * (int)sizeof(float);
    cudaFuncSetAttribute(attn_kernel, cudaFuncAttributeMaxDynamicSharedMemorySize, smem);
    attn_kernel<<<dim3(NN / 64, BB * HH), 256, smem>>>();

    // 3) Output projection + bias
    out_gemm<<<dim3(DIM / 64, NTOK / 64), 256>>>(Wfc, bfc, out);
}

// round 3
// speedup vs baseline: 1.2685x; 1.2685x over previous
#include <cuda_runtime.h>
#include <cstdint>
#include <math.h>

#define BB 8
#define NN 1024
#define HH 12
#define DHD 64
#define DIM 768
#define DH  768
#define E3  2304
#define NTOK (BB*NN)
#define KTOT 768

// Scratch (device globals; no runtime allocation allowed)
__device__ float g_qkv[(size_t)NTOK * E3];   // [m, 3*DH] qkv projection output
__device__ float g_o[(size_t)NTOK * DH];     // [m, DH] attention output

// ===========================================================================
// Split-tf32 GEMM on warp MMA (HMMA): C[m,n] = sum_k A[m,k]*B[n,k] (+bias[n])
// Block tile 128x128, 8 warps (64x32 warp tiles), K-chunk 32.
// Each fp32 split: hi = top-10-mantissa (exact tf32), lo = residual.
// 3 passes: hi*hi + hi*lo + lo*hi  -> ~2^-21 elementwise error.
// ===========================================================================
#define SROW 36                       // smem row stride in floats (conflict-free)
#define SMAT (128 * SROW)             // floats per matrix buffer
#define SMEM_MM (4 * SMAT * 4)        // bytes: Ahi, Alo, Bhi, Blo

__device__ __forceinline__ uint32_t hi_bits(float x) {
    return __float_as_uint(x) & 0xFFFFE000u;
}

__device__ __forceinline__ void mma_tf32(float* d, const uint32_t* a,
                                         const uint32_t* b) {
    asm volatile(
        "mma.sync.aligned.m16n8k8.row.col.f32.tf32.tf32.f32 "
        "{%0,%1,%2,%3}, {%4,%5,%6,%7}, {%8,%9}, {%0,%1,%2,%3};"
        : "+f"(d[0]), "+f"(d[1]), "+f"(d[2]), "+f"(d[3])
        : "r"(a[0]), "r"(a[1]), "r"(a[2]), "r"(a[3]), "r"(b[0]), "r"(b[1]));
}

__global__ __launch_bounds__(256) void mm_hmma(const float* __restrict__ A,
                                               const float* __restrict__ Bm,
                                               const float* __restrict__ bias,
                                               float* __restrict__ C, int ldc) {
    extern __shared__ float smem[];
    float* sAh = smem;
    float* sAl = smem + SMAT;
    float* sBh = smem + 2 * SMAT;
    float* sBl = smem + 3 * SMAT;

    const int tid = threadIdx.x;
    const int wid = tid >> 5, lane = tid & 31;
    const int gid = lane >> 2, tig = lane & 3;
    const int wm = wid & 1;            // 2 m-halves of 64
    const int wn = wid >> 1;           // 4 n-quarters of 32
    const int m0 = blockIdx.y * 128;
    const int n0 = blockIdx.x * 128;

    float acc[4][4][4] = {};           // [t m16][u n8][4]

    for (int k0 = 0; k0 < KTOT; k0 += 32) {
        if (k0) __syncthreads();
        // Stage chunk: 128 rows x 32 floats per matrix, split hi/lo
        #pragma unroll
        for (int p = 0; p < 4; p++) {
            const int j = tid + p * 256;       // 0..1023 float4 slots
            const int r = j >> 3, c4 = (j & 7) * 4;
            float4 va = *(const float4*)(A + (size_t)(m0 + r) * KTOT + k0 + c4);
            float4 vb = *(const float4*)(Bm + (size_t)(n0 + r) * KTOT + k0 + c4);
            float4 ha = make_float4(__uint_as_float(hi_bits(va.x)),
                                    __uint_as_float(hi_bits(va.y)),
                                    __uint_as_float(hi_bits(va.z)),
                                    __uint_as_float(hi_bits(va.w)));
            float4 hb = make_float4(__uint_as_float(hi_bits(vb.x)),
                                    __uint_as_float(hi_bits(vb.y)),
                                    __uint_as_float(hi_bits(vb.z)),
                                    __uint_as_float(hi_bits(vb.w)));
            const int s = r * SROW + c4;
            *(float4*)(sAh + s) = ha;
            *(float4*)(sAl + s) = make_float4(va.x - ha.x, va.y - ha.y,
                                              va.z - ha.z, va.w - ha.w);
            *(float4*)(sBh + s) = hb;
            *(float4*)(sBl + s) = make_float4(vb.x - hb.x, vb.y - hb.y,
                                              vb.z - hb.z, vb.w - hb.w);
        }
        __syncthreads();

        #pragma unroll
        for (int kk = 0; kk < 32; kk += 8) {
            uint32_t af[4][4], bh[4][2], bl[4][2];
            // A_hi fragments (4 m16 tiles)
            #pragma unroll
            for (int t = 0; t < 4; t++) {
                const int rb = (wm * 64 + t * 16 + gid) * SROW + kk + tig;
                af[t][0] = __float_as_uint(sAh[rb]);
                af[t][1] = __float_as_uint(sAh[rb + 8 * SROW]);
                af[t][2] = __float_as_uint(sAh[rb + 4]);
                af[t][3] = __float_as_uint(sAh[rb + 8 * SROW + 4]);
            }
            // B_hi / B_lo fragments (4 n8 tiles)
            #pragma unroll
            for (int u = 0; u < 4; u++) {
                const int rb = (wn * 32 + u * 8 + gid) * SROW + kk + tig;
                bh[u][0] = __float_as_uint(sBh[rb]);
                bh[u][1] = __float_as_uint(sBh[rb + 4]);
                bl[u][0] = __float_as_uint(sBl[rb]);
                bl[u][1] = __float_as_uint(sBl[rb + 4]);
            }
            // pass 1: Ahi * Bhi
            #pragma unroll
            for (int t = 0; t < 4; t++)
                #pragma unroll
                for (int u = 0; u < 4; u++)
                    mma_tf32(acc[t][u], af[t], bh[u]);
            // pass 2: Ahi * Blo
            #pragma unroll
            for (int t = 0; t < 4; t++)
                #pragma unroll
                for (int u = 0; u < 4; u++)
                    mma_tf32(acc[t][u], af[t], bl[u]);
            // pass 3: Alo * Bhi (overwrite af)
            #pragma unroll
            for (int t = 0; t < 4; t++) {
                const int rb = (wm * 64 + t * 16 + gid) * SROW + kk + tig;
                af[t][0] = __float_as_uint(sAl[rb]);
                af[t][1] = __float_as_uint(sAl[rb + 8 * SROW]);
                af[t][2] = __float_as_uint(sAl[rb + 4]);
                af[t][3] = __float_as_uint(sAl[rb + 8 * SROW + 4]);
            }
            #pragma unroll
            for (int t = 0; t < 4; t++)
                #pragma unroll
                for (int u = 0; u < 4; u++)
                    mma_tf32(acc[t][u], af[t], bh[u]);
        }
    }

    // Epilogue: c0,c1 -> (row gid, cols 2tig,2tig+1); c2,c3 -> row gid+8
    const int rbase = m0 + wm * 64;
    const int cbase = n0 + wn * 32;
    #pragma unroll
    for (int t = 0; t < 4; t++) {
        #pragma unroll
        for (int u = 0; u < 4; u++) {
            const int c = cbase + u * 8 + tig * 2;
            float b0 = 0.f, b1 = 0.f;
            if (bias) { b0 = bias[c]; b1 = bias[c + 1]; }
            const int r0 = rbase + t * 16 + gid;
            float2 v0 = make_float2(acc[t][u][0] + b0, acc[t][u][1] + b1);
            float2 v1 = make_float2(acc[t][u][2] + b0, acc[t][u][3] + b1);
            *(float2*)(C + (size_t)r0 * ldc + c) = v0;
            *(float2*)(C + (size_t)(r0 + 8) * ldc + c) = v1;
        }
    }
}

// ===========================================================================
// Flash attention per (b*h, q-tile of 64). fp32 SIMT; reads flat qkv [m,2304].
// ===========================================================================
__global__ __launch_bounds__(256) void attn_kernel() {
    extern __shared__ float sm[];
    float* Qs = sm;                 // [64 d][64 r]
    float* Ks = Qs + 64 * 64;       // [64 d][64 c]
    float* Vs = Ks + 64 * 64;       // [64 c][64 d]
    float* Ps = Vs + 64 * 64;       // [64 r][64 c]
    float* m_row = Ps + 64 * 64;
    float* l_row = m_row + 64;

    const int bh = blockIdx.y;
    const int q0 = blockIdx.x * 64;
    const int tid = threadIdx.x;
    const int tm = tid >> 4;
    const int tn = tid & 15;
    const int lr = tid >> 2;
    const int ld0 = (tid & 3) * 16;

    const int b = bh / HH;
    const int h = bh - b * HH;
    const float* Qg = g_qkv + ((size_t)(b * NN + q0)) * E3 + h * 192;
    const float* Kg = g_qkv + ((size_t)(b * NN)) * E3 + h * 192 + 64;
    const float* Vg = g_qkv + ((size_t)(b * NN)) * E3 + h * 192 + 128;

    #pragma unroll
    for (int c4 = 0; c4 < 4; c4++) {
        float4 v = *(const float4*)(Qg + (size_t)lr * E3 + ld0 + c4 * 4);
        Qs[(ld0 + c4 * 4 + 0) * 64 + lr] = v.x;
        Qs[(ld0 + c4 * 4 + 1) * 64 + lr] = v.y;
        Qs[(ld0 + c4 * 4 + 2) * 64 + lr] = v.z;
        Qs[(ld0 + c4 * 4 + 3) * 64 + lr] = v.w;
    }
    if (tid < 64) { m_row[tid] = -1e30f; l_row[tid] = 0.f; }

    float o_acc[4][4] = {};
    __syncthreads();

    for (int kt = 0; kt < 16; kt++) {
        const float* Kt = Kg + (size_t)(kt * 64) * E3;
        const float* Vt = Vg + (size_t)(kt * 64) * E3;
        #pragma unroll
        for (int c4 = 0; c4 < 4; c4++) {
            float4 kv = *(const float4*)(Kt + (size_t)lr * E3 + ld0 + c4 * 4);
            Ks[(ld0 + c4 * 4 + 0) * 64 + lr] = kv.x;
            Ks[(ld0 + c4 * 4 + 1) * 64 + lr] = kv.y;
            Ks[(ld0 + c4 * 4 + 2) * 64 + lr] = kv.z;
            Ks[(ld0 + c4 * 4 + 3) * 64 + lr] = kv.w;
            float4 vv = *(const float4*)(Vt + (size_t)lr * E3 + ld0 + c4 * 4);
            *(float4*)&Vs[lr * 64 + ld0 + c4 * 4] = vv;
        }
        __syncthreads();

        float s[4][4] = {};
        #pragma unroll 8
        for (int d = 0; d < 64; d++) {
            float4 a = *(const float4*)&Qs[d * 64 + tm * 4];
            float4 bq = *(const float4*)&Ks[d * 64 + tn * 4];
            float af[4] = {a.x, a.y, a.z, a.w};
            float bf[4] = {bq.x, bq.y, bq.z, bq.w};
            #pragma unroll
            for (int i = 0; i < 4; i++)
                #pragma unroll
                for (int j = 0; j < 4; j++)
                    s[i][j] = fmaf(af[i], bf[j], s[i][j]);
        }
        #pragma unroll
        for (int i = 0; i < 4; i++)
            #pragma unroll
            for (int j = 0; j < 4; j++)
                s[i][j] *= 8.0f;

        float m_old[4];
        #pragma unroll
        for (int i = 0; i < 4; i++) m_old[i] = m_row[tm * 4 + i];
        __syncwarp();

        float f[4];
        #pragma unroll
        for (int i = 0; i < 4; i++) {
            float mt = fmaxf(fmaxf(s[i][0], s[i][1]), fmaxf(s[i][2], s[i][3]));
            #pragma unroll
            for (int off = 1; off < 16; off <<= 1)
                mt = fmaxf(mt, __shfl_xor_sync(0xffffffffu, mt, off));
            const float mn = fmaxf(m_old[i], mt);
            float ls = 0.f;
            #pragma unroll
            for (int j = 0; j < 4; j++) {
                s[i][j] = __expf(s[i][j] - mn);
                ls += s[i][j];
            }
            #pragma unroll
            for (int off = 1; off < 16; off <<= 1)
                ls += __shfl_xor_sync(0xffffffffu, ls, off);
            f[i] = __expf(m_old[i] - mn);
            if (tn == 0) {
                m_row[tm * 4 + i] = mn;
                l_row[tm * 4 + i] = l_row[tm * 4 + i] * f[i] + ls;
            }
            *(float4*)&Ps[(tm * 4 + i) * 64 + tn * 4] =
                make_float4(s[i][0], s[i][1], s[i][2], s[i][3]);
        }
        __syncthreads();

        #pragma unroll
        for (int i = 0; i < 4; i++)
            #pragma unroll
            for (int j = 0; j < 4; j++)
                o_acc[i][j] *= f[i];

        #pragma unroll 8
        for (int c = 0; c < 64; c++) {
            float4 bq = *(const float4*)&Vs[c * 64 + tn * 4];
            float bf[4] = {bq.x, bq.y, bq.z, bq.w};
            float a0 = Ps[(tm * 4 + 0) * 64 + c];
            float a1 = Ps[(tm * 4 + 1) * 64 + c];
            float a2 = Ps[(tm * 4 + 2) * 64 + c];
            float a3 = Ps[(tm * 4 + 3) * 64 + c];
            #pragma unroll
            for (int j = 0; j < 4; j++) {
                o_acc[0][j] = fmaf(a0, bf[j], o_acc[0][j]);
                o_acc[1][j] = fmaf(a1, bf[j], o_acc[1][j]);
                o_acc[2][j] = fmaf(a2, bf[j], o_acc[2][j]);
                o_acc[3][j] = fmaf(a3, bf[j], o_acc[3][j]);
            }
        }
        __syncthreads();
    }

    #pragma unroll
    for (int i = 0; i < 4; i++) {
        const int r = tm * 4 + i;
        const float il = 1.0f / l_row[r];
        float4 o = make_float4(o_acc[i][0] * il, o_acc[i][1] * il,
                               o_acc[i][2] * il, o_acc[i][3] * il);
        size_t idx = ((size_t)(b * NN + q0 + r)) * DH + h * DHD + tn * 4;
        *(float4*)&g_o[idx] = o;
    }
}

// ===========================================================================
extern "C" void kernel_launch(void* const* d_in, const int* in_sizes, int n_in,
                              void* d_out, int out_size) {
    const float* img  = (const float*)d_in[0];   // [8,1024,768]
    const float* Wqkv = (const float*)d_in[1];   // [2304,768]
    const float* Wfc  = (const float*)d_in[2];   // [768,768]
    const float* bfc  = (const float*)d_in[3];   // [768]
    float* out = (float*)d_out;                  // [8,1024,768]

    void* qkvp = nullptr;
    void* op = nullptr;
    cudaGetSymbolAddress(&qkvp, g_qkv);
    cudaGetSymbolAddress(&op, g_o);

    cudaFuncSetAttribute(mm_hmma, cudaFuncAttributeMaxDynamicSharedMemorySize,
                         SMEM_MM);

    // 1) QKV projection: [8192,2304] = img[8192,768] @ Wqkv^T
    mm_hmma<<<dim3(E3 / 128, NTOK / 128), 256, SMEM_MM>>>(img, Wqkv, nullptr,
                                                          (float*)qkvp, E3);

    // 2) Flash attention (fp32)
    const int smem_attn = (4 * 64 * 64 + 128) * (int)sizeof(float);
    cudaFuncSetAttribute(attn_kernel, cudaFuncAttributeMaxDynamicSharedMemorySize,
                         smem_attn);
    attn_kernel<<<dim3(NN / 64, BB * HH), 256, smem_attn>>>();

    // 3) Output projection + bias: [8192,768] = g_o[8192,768] @ Wfc^T + b
    mm_hmma<<<dim3(DIM / 128, NTOK / 128), 256, SMEM_MM>>>((const float*)op, Wfc,
                                                           bfc, out, DIM);
}

// round 4
// speedup vs baseline: 1.2800x; 1.0091x over previous
#include <cuda_runtime.h>
#include <cstdint>
#include <math.h>

#define BB 8
#define NN 1024
#define HH 12
#define DHD 64
#define DIM 768
#define DH  768
#define E3  2304
#define NTOK (BB*NN)
#define KTOT 768
#define NBH (BB*HH)   // 96

// Scratch (device globals; no runtime allocation allowed)
__device__ float g_qkv[(size_t)NTOK * E3];
__device__ float g_o[(size_t)NTOK * DH];
// pre-split planes for attention (hi/lo split, k-permuted within 8-groups)
__device__ float g_qsh[(size_t)NBH * NN * DHD];
__device__ float g_qsl[(size_t)NBH * NN * DHD];
__device__ float g_ksh[(size_t)NBH * NN * DHD];
__device__ float g_ksl[(size_t)NBH * NN * DHD];
__device__ float g_vth[(size_t)NBH * DHD * NN];   // [bh][dim][key]
__device__ float g_vtl[(size_t)NBH * DHD * NN];

__device__ __forceinline__ uint32_t hi_bits(float x) {
    return __float_as_uint(x) & 0xFFFFE000u;
}
__device__ __forceinline__ float hif(float x) {
    return __uint_as_float(hi_bits(x));
}
__device__ __forceinline__ uint32_t fau(float x) { return __float_as_uint(x); }

__device__ __forceinline__ void mma_tf32(float* d, const uint32_t* a,
                                         const uint32_t* b) {
    asm volatile(
        "mma.sync.aligned.m16n8k8.row.col.f32.tf32.tf32.f32 "
        "{%0,%1,%2,%3}, {%4,%5,%6,%7}, {%8,%9}, {%0,%1,%2,%3};"
        : "+f"(d[0]), "+f"(d[1]), "+f"(d[2]), "+f"(d[3])
        : "r"(a[0]), "r"(a[1]), "r"(a[2]), "r"(a[3]), "r"(b[0]), "r"(b[1]));
}

// ===========================================================================
// Split-tf32 GEMM on warp MMA (unchanged from round 3 — proven).
// ===========================================================================
#define SROW 36
#define SMAT (128 * SROW)
#define SMEM_MM (4 * SMAT * 4)

__global__ __launch_bounds__(256) void mm_hmma(const float* __restrict__ A,
                                               const float* __restrict__ Bm,
                                               const float* __restrict__ bias,
                                               float* __restrict__ C, int ldc) {
    extern __shared__ float smem[];
    float* sAh = smem;
    float* sAl = smem + SMAT;
    float* sBh = smem + 2 * SMAT;
    float* sBl = smem + 3 * SMAT;

    const int tid = threadIdx.x;
    const int wid = tid >> 5, lane = tid & 31;
    const int gid = lane >> 2, tig = lane & 3;
    const int wm = wid & 1;
    const int wn = wid >> 1;
    const int m0 = blockIdx.y * 128;
    const int n0 = blockIdx.x * 128;

    float acc[4][4][4] = {};

    for (int k0 = 0; k0 < KTOT; k0 += 32) {
        if (k0) __syncthreads();
        #pragma unroll
        for (int p = 0; p < 4; p++) {
            const int j = tid + p * 256;
            const int r = j >> 3, c4 = (j & 7) * 4;
            float4 va = *(const float4*)(A + (size_t)(m0 + r) * KTOT + k0 + c4);
            float4 vb = *(const float4*)(Bm + (size_t)(n0 + r) * KTOT + k0 + c4);
            float4 ha = make_float4(hif(va.x), hif(va.y), hif(va.z), hif(va.w));
            float4 hb = make_float4(hif(vb.x), hif(vb.y), hif(vb.z), hif(vb.w));
            const int s = r * SROW + c4;
            *(float4*)(sAh + s) = ha;
            *(float4*)(sAl + s) = make_float4(va.x - ha.x, va.y - ha.y,
                                              va.z - ha.z, va.w - ha.w);
            *(float4*)(sBh + s) = hb;
            *(float4*)(sBl + s) = make_float4(vb.x - hb.x, vb.y - hb.y,
                                              vb.z - hb.z, vb.w - hb.w);
        }
        __syncthreads();

        #pragma unroll
        for (int kk = 0; kk < 32; kk += 8) {
            uint32_t af[4][4], bh[4][2], bl[4][2];
            #pragma unroll
            for (int t = 0; t < 4; t++) {
                const int rb = (wm * 64 + t * 16 + gid) * SROW + kk + tig;
                af[t][0] = fau(sAh[rb]);
                af[t][1] = fau(sAh[rb + 8 * SROW]);
                af[t][2] = fau(sAh[rb + 4]);
                af[t][3] = fau(sAh[rb + 8 * SROW + 4]);
            }
            #pragma unroll
            for (int u = 0; u < 4; u++) {
                const int rb = (wn * 32 + u * 8 + gid) * SROW + kk + tig;
                bh[u][0] = fau(sBh[rb]);
                bh[u][1] = fau(sBh[rb + 4]);
                bl[u][0] = fau(sBl[rb]);
                bl[u][1] = fau(sBl[rb + 4]);
            }
            #pragma unroll
            for (int t = 0; t < 4; t++)
                #pragma unroll
                for (int u = 0; u < 4; u++)
                    mma_tf32(acc[t][u], af[t], bh[u]);
            #pragma unroll
            for (int t = 0; t < 4; t++)
                #pragma unroll
                for (int u = 0; u < 4; u++)
                    mma_tf32(acc[t][u], af[t], bl[u]);
            #pragma unroll
            for (int t = 0; t < 4; t++) {
                const int rb = (wm * 64 + t * 16 + gid) * SROW + kk + tig;
                af[t][0] = fau(sAl[rb]);
                af[t][1] = fau(sAl[rb + 8 * SROW]);
                af[t][2] = fau(sAl[rb + 4]);
                af[t][3] = fau(sAl[rb + 8 * SROW + 4]);
            }
            #pragma unroll
            for (int t = 0; t < 4; t++)
                #pragma unroll
                for (int u = 0; u < 4; u++)
                    mma_tf32(acc[t][u], af[t], bh[u]);
        }
    }

    const int rbase = m0 + wm * 64;
    const int cbase = n0 + wn * 32;
    #pragma unroll
    for (int t = 0; t < 4; t++) {
        #pragma unroll
        for (int u = 0; u < 4; u++) {
            const int c = cbase + u * 8 + tig * 2;
            float b0 = 0.f, b1 = 0.f;
            if (bias) { b0 = bias[c]; b1 = bias[c + 1]; }
            const int r0 = rbase + t * 16 + gid;
            *(float2*)(C + (size_t)r0 * ldc + c) =
                make_float2(acc[t][u][0] + b0, acc[t][u][1] + b1);
            *(float2*)(C + (size_t)(r0 + 8) * ldc + c) =
                make_float2(acc[t][u][2] + b0, acc[t][u][3] + b1);
        }
    }
}

// ===========================================================================
// Pre-pass 1: split Q (x8) and K into hi/lo planes, k-permuted within
// 8-groups: pos(r) = (r&3)*2 + (r>>2)  (makes (tig, tig+4) adjacent pairs).
// ===========================================================================
__global__ __launch_bounds__(256) void prep_qk() {
    const int j = blockIdx.x * 256 + threadIdx.x;   // NBH*NN*16 threads
    const int c4 = (j & 15) * 4;
    const int bt = j >> 4;                          // bh*1024 + tok
    const int bh = bt >> 10, tok = bt & 1023;
    const int b = bh / HH, h = bh - b * HH;
    const float* base = g_qkv + ((size_t)(b * NN + tok)) * E3 + h * 192;
    float4 q = *(const float4*)(base + c4);
    float4 k = *(const float4*)(base + 64 + c4);
    const size_t og = (size_t)bt * 64 + (c4 & ~7);
    const float* qf = (const float*)&q;
    const float* kf = (const float*)&k;
    #pragma unroll
    for (int i = 0; i < 4; i++) {
        const int r = (c4 + i) & 7;
        const int p = ((r & 3) << 1) | (r >> 2);
        float qv = qf[i] * 8.0f;            // fold the x8 scale (exact)
        float qh = hif(qv);
        g_qsh[og + p] = qh;
        g_qsl[og + p] = qv - qh;
        float kv = kf[i];
        float kh = hif(kv);
        g_ksh[og + p] = kh;
        g_ksl[og + p] = kv - kh;
    }
}

// ===========================================================================
// Pre-pass 2: V -> V^T [bh][dim][key], split hi/lo, key-permuted in 8-groups.
// ===========================================================================
__global__ __launch_bounds__(256) void prep_v() {
    __shared__ float sv[64][68];
    const int bh = blockIdx.y;
    const int kt = blockIdx.x;
    const int b = bh / HH, h = bh - b * HH;
    const int tid = threadIdx.x;
    #pragma unroll
    for (int p = 0; p < 4; p++) {
        const int j = tid + p * 256;
        const int key = j >> 4, c4 = (j & 15) * 4;
        float4 v = *(const float4*)(g_qkv +
            ((size_t)(b * NN + kt * 64 + key)) * E3 + h * 192 + 128 + c4);
        *(float4*)&sv[key][c4] = v;
    }
    __syncthreads();
    #pragma unroll
    for (int i = 0; i < 4; i++) {
        const int d = (tid >> 4) + i * 16;
        const int key4 = (tid & 15) * 4;
        const size_t ob = ((size_t)bh * 64 + d) * NN + kt * 64 + (key4 & ~7);
        #pragma unroll
        for (int e = 0; e < 4; e++) {
            const int r = (key4 + e) & 7;
            const int p = ((r & 3) << 1) | (r >> 2);
            float v = sv[key4 + e][d];
            float vh = hif(v);
            g_vth[ob + p] = vh;
            g_vtl[ob + p] = v - vh;
        }
    }
}

// ===========================================================================
// Flash attention with split-tf32 HMMA.
// Block = (bh, q-tile of 128). 8 warps, warp w owns q-rows 16w..16w+15.
// S = Q K^T (3-pass), warp-local online softmax, O += P V (3-pass).
// ===========================================================================
#define ASTR 68
#define ATTN_SMEM (52224 * 4)   // floats below

__global__ __launch_bounds__(256) void attn_hmma() {
    extern __shared__ float sm[];
    float* sQh = sm;                 // 128*68
    float* sQl = sQh + 8704;
    float* sKh = sQl + 8704;         // 64*68
    float* sKl = sKh + 4352;
    float* sVh = sKl + 4352;         // [dim][keypos]
    float* sVl = sVh + 4352;
    float* sPh = sVl + 4352;         // 128*68 (unpermuted cols)
    float* sPl = sPh + 8704;

    const int bh = blockIdx.y;
    const int q0 = blockIdx.x * 128;
    const int tid = threadIdx.x;
    const int wid = tid >> 5, lane = tid & 31;
    const int gid = lane >> 2, tig = lane & 3;
    const int b = bh / HH, h = bh - b * HH;
    const int r0 = wid * 16 + gid;

    // Stage Q tile (pre-split, pre-scaled, permuted): pure float4 copies
    {
        const float* qh = g_qsh + ((size_t)bh * NN + q0) * 64;
        const float* ql = g_qsl + ((size_t)bh * NN + q0) * 64;
        #pragma unroll
        for (int p = 0; p < 8; p++) {
            const int j = tid + p * 256;
            const int r = j >> 4, c4 = (j & 15) * 4;
            *(float4*)&sQh[r * ASTR + c4] = *(const float4*)(qh + r * 64 + c4);
            *(float4*)&sQl[r * ASTR + c4] = *(const float4*)(ql + r * 64 + c4);
        }
    }

    float oa[8][4] = {};
    float mrow0 = -1e30f, mrow1 = -1e30f, lrow0 = 0.f, lrow1 = 0.f;

    for (int kt = 0; kt < 16; kt++) {
        // Stage K and V^T tiles
        {
            const float* kh = g_ksh + ((size_t)bh * NN + kt * 64) * 64;
            const float* kl = g_ksl + ((size_t)bh * NN + kt * 64) * 64;
            const float* vh = g_vth + ((size_t)bh * 64) * NN + kt * 64;
            const float* vl = g_vtl + ((size_t)bh * 64) * NN + kt * 64;
            #pragma unroll
            for (int p = 0; p < 4; p++) {
                const int j = tid + p * 256;
                const int r = j >> 4, c4 = (j & 15) * 4;
                *(float4*)&sKh[r * ASTR + c4] = *(const float4*)(kh + r * 64 + c4);
                *(float4*)&sKl[r * ASTR + c4] = *(const float4*)(kl + r * 64 + c4);
                *(float4*)&sVh[r * ASTR + c4] = *(const float4*)(vh + (size_t)r * NN + c4);
                *(float4*)&sVl[r * ASTR + c4] = *(const float4*)(vl + (size_t)r * NN + c4);
            }
        }
        __syncthreads();

        // ---- S = Q K^T (3-pass split) ----
        float s[8][4] = {};
        #pragma unroll
        for (int kk = 0; kk < 64; kk += 8) {
            float2 aqh0 = *(float2*)&sQh[r0 * ASTR + kk + 2 * tig];
            float2 aqh1 = *(float2*)&sQh[(r0 + 8) * ASTR + kk + 2 * tig];
            float2 aql0 = *(float2*)&sQl[r0 * ASTR + kk + 2 * tig];
            float2 aql1 = *(float2*)&sQl[(r0 + 8) * ASTR + kk + 2 * tig];
            uint32_t ah[4] = {fau(aqh0.x), fau(aqh1.x), fau(aqh0.y), fau(aqh1.y)};
            uint32_t al[4] = {fau(aql0.x), fau(aql1.x), fau(aql0.y), fau(aql1.y)};
            #pragma unroll
            for (int u = 0; u < 8; u++) {
                const int n = u * 8 + gid;
                float2 bh2 = *(float2*)&sKh[n * ASTR + kk + 2 * tig];
                float2 bl2 = *(float2*)&sKl[n * ASTR + kk + 2 * tig];
                uint32_t bhf[2] = {fau(bh2.x), fau(bh2.y)};
                uint32_t blf[2] = {fau(bl2.x), fau(bl2.y)};
                mma_tf32(s[u], ah, bhf);
                mma_tf32(s[u], ah, blf);
                mma_tf32(s[u], al, bhf);
            }
        }

        // ---- warp-local online softmax ----
        float mt0 = -1e30f, mt1 = -1e30f;
        #pragma unroll
        for (int u = 0; u < 8; u++) {
            mt0 = fmaxf(mt0, fmaxf(s[u][0], s[u][1]));
            mt1 = fmaxf(mt1, fmaxf(s[u][2], s[u][3]));
        }
        #pragma unroll
        for (int off = 1; off < 4; off <<= 1) {
            mt0 = fmaxf(mt0, __shfl_xor_sync(0xffffffffu, mt0, off));
            mt1 = fmaxf(mt1, __shfl_xor_sync(0xffffffffu, mt1, off));
        }
        const float mn0 = fmaxf(mrow0, mt0);
        const float mn1 = fmaxf(mrow1, mt1);
        const float f0 = __expf(mrow0 - mn0);
        const float f1 = __expf(mrow1 - mn1);
        float ls0 = 0.f, ls1 = 0.f;
        #pragma unroll
        for (int u = 0; u < 8; u++) {
            float p00 = __expf(s[u][0] - mn0);
            float p01 = __expf(s[u][1] - mn0);
            float p10 = __expf(s[u][2] - mn1);
            float p11 = __expf(s[u][3] - mn1);
            ls0 += p00 + p01;
            ls1 += p10 + p11;
            float h00 = hif(p00), h01 = hif(p01), h10 = hif(p10), h11 = hif(p11);
            const int cb = u * 8 + 2 * tig;
            *(float2*)&sPh[r0 * ASTR + cb] = make_float2(h00, h01);
            *(float2*)&sPl[r0 * ASTR + cb] = make_float2(p00 - h00, p01 - h01);
            *(float2*)&sPh[(r0 + 8) * ASTR + cb] = make_float2(h10, h11);
            *(float2*)&sPl[(r0 + 8) * ASTR + cb] = make_float2(p10 - h10, p11 - h11);
        }
        #pragma unroll
        for (int off = 1; off < 4; off <<= 1) {
            ls0 += __shfl_xor_sync(0xffffffffu, ls0, off);
            ls1 += __shfl_xor_sync(0xffffffffu, ls1, off);
        }
        lrow0 = lrow0 * f0 + ls0;  mrow0 = mn0;
        lrow1 = lrow1 * f1 + ls1;  mrow1 = mn1;

        // rescale O accumulator
        #pragma unroll
        for (int u = 0; u < 8; u++) {
            oa[u][0] *= f0; oa[u][1] *= f0;
            oa[u][2] *= f1; oa[u][3] *= f1;
        }
        __syncwarp();   // P is consumed only within this warp

        // ---- O += P V (3-pass split) ----
        #pragma unroll
        for (int kk = 0; kk < 64; kk += 8) {
            const int rb = r0 * ASTR + kk + tig;
            uint32_t ah[4] = {fau(sPh[rb]), fau(sPh[rb + 8 * ASTR]),
                              fau(sPh[rb + 4]), fau(sPh[rb + 8 * ASTR + 4])};
            uint32_t al[4] = {fau(sPl[rb]), fau(sPl[rb + 8 * ASTR]),
                              fau(sPl[rb + 4]), fau(sPl[rb + 8 * ASTR + 4])};
            #pragma unroll
            for (int u = 0; u < 8; u++) {
                const int n = u * 8 + gid;
                float2 bh2 = *(float2*)&sVh[n * ASTR + kk + 2 * tig];
                float2 bl2 = *(float2*)&sVl[n * ASTR + kk + 2 * tig];
                uint32_t bhf[2] = {fau(bh2.x), fau(bh2.y)};
                uint32_t blf[2] = {fau(bl2.x), fau(bl2.y)};
                mma_tf32(oa[u], ah, bhf);
                mma_tf32(oa[u], ah, blf);
                mma_tf32(oa[u], al, bhf);
            }
        }
        __syncthreads();   // protect sK/sV before next staging
    }

    // Epilogue: O /= l, write merged-heads layout
    const float il0 = 1.f / lrow0;
    const float il1 = 1.f / lrow1;
    #pragma unroll
    for (int u = 0; u < 8; u++) {
        const int col = h * 64 + u * 8 + 2 * tig;
        *(float2*)&g_o[((size_t)(b * NN + q0 + r0)) * DH + col] =
            make_float2(oa[u][0] * il0, oa[u][1] * il0);
        *(float2*)&g_o[((size_t)(b * NN + q0 + r0 + 8)) * DH + col] =
            make_float2(oa[u][2] * il1, oa[u][3] * il1);
    }
}

// ===========================================================================
extern "C" void kernel_launch(void* const* d_in, const int* in_sizes, int n_in,
                              void* d_out, int out_size) {
    const float* img  = (const float*)d_in[0];   // [8,1024,768]
    const float* Wqkv = (const float*)d_in[1];   // [2304,768]
    const float* Wfc  = (const float*)d_in[2];   // [768,768]
    const float* bfc  = (const float*)d_in[3];   // [768]
    float* out = (float*)d_out;                  // [8,1024,768]

    void* qkvp = nullptr;
    void* op = nullptr;
    cudaGetSymbolAddress(&qkvp, g_qkv);
    cudaGetSymbolAddress(&op, g_o);

    cudaFuncSetAttribute(mm_hmma, cudaFuncAttributeMaxDynamicSharedMemorySize,
                         SMEM_MM);
    cudaFuncSetAttribute(attn_hmma, cudaFuncAttributeMaxDynamicSharedMemorySize,
                         ATTN_SMEM);

    // 1) QKV projection: [8192,2304] = img @ Wqkv^T
    mm_hmma<<<dim3(E3 / 128, NTOK / 128), 256, SMEM_MM>>>(img, Wqkv, nullptr,
                                                          (float*)qkvp, E3);

    // 2) Pre-split/permute Q,K and transpose/split V
    prep_qk<<<NBH * NN * 16 / 256, 256>>>();
    prep_v<<<dim3(16, NBH), 256>>>();

    // 3) Flash attention (split-tf32 HMMA)
    attn_hmma<<<dim3(NN / 128, NBH), 256, ATTN_SMEM>>>();

    // 4) Output projection + bias
    mm_hmma<<<dim3(DIM / 128, NTOK / 128), 256, SMEM_MM>>>((const float*)op, Wfc,
                                                           bfc, out, DIM);
}

// round 5
// speedup vs baseline: 1.3465x; 1.0520x over previous
#include <cuda_runtime.h>
#include <cstdint>
#include <math.h>

#define BB 8
#define NN 1024
#define HH 12
#define DHD 64
#define DIM 768
#define DH  768
#define E3  2304
#define NTOK (BB*NN)
#define KTOT 768
#define NBH (BB*HH)   // 96

// Scratch (device globals; no runtime allocation allowed)
__device__ float g_qkv[(size_t)NTOK * E3];
__device__ float g_o[(size_t)NTOK * DH];
__device__ float g_vt[(size_t)NBH * DHD * NN];   // [bh][dim][key], unsplit

__device__ __forceinline__ uint32_t hi_bits(float x) {
    return __float_as_uint(x) & 0xFFFFE000u;
}
__device__ __forceinline__ float hif(float x) {
    return __uint_as_float(hi_bits(x));
}
__device__ __forceinline__ uint32_t fau(float x) { return __float_as_uint(x); }

__device__ __forceinline__ void mma_tf32(float* d, const uint32_t* a,
                                         const uint32_t* b) {
    asm volatile(
        "mma.sync.aligned.m16n8k8.row.col.f32.tf32.tf32.f32 "
        "{%0,%1,%2,%3}, {%4,%5,%6,%7}, {%8,%9}, {%0,%1,%2,%3};"
        : "+f"(d[0]), "+f"(d[1]), "+f"(d[2]), "+f"(d[3])
        : "r"(a[0]), "r"(a[1]), "r"(a[2]), "r"(a[3]), "r"(b[0]), "r"(b[1]));
}

// ===========================================================================
// Split-tf32 GEMM on warp MMA (unchanged — proven at 57% tensor).
// ===========================================================================
#define SROW 36
#define SMAT (128 * SROW)
#define SMEM_MM (4 * SMAT * 4)

__global__ __launch_bounds__(256) void mm_hmma(const float* __restrict__ A,
                                               const float* __restrict__ Bm,
                                               const float* __restrict__ bias,
                                               float* __restrict__ C, int ldc) {
    extern __shared__ float smem[];
    float* sAh = smem;
    float* sAl = smem + SMAT;
    float* sBh = smem + 2 * SMAT;
    float* sBl = smem + 3 * SMAT;

    const int tid = threadIdx.x;
    const int wid = tid >> 5, lane = tid & 31;
    const int gid = lane >> 2, tig = lane & 3;
    const int wm = wid & 1;
    const int wn = wid >> 1;
    const int m0 = blockIdx.y * 128;
    const int n0 = blockIdx.x * 128;

    float acc[4][4][4] = {};

    for (int k0 = 0; k0 < KTOT; k0 += 32) {
        if (k0) __syncthreads();
        #pragma unroll
        for (int p = 0; p < 4; p++) {
            const int j = tid + p * 256;
            const int r = j >> 3, c4 = (j & 7) * 4;
            float4 va = *(const float4*)(A + (size_t)(m0 + r) * KTOT + k0 + c4);
            float4 vb = *(const float4*)(Bm + (size_t)(n0 + r) * KTOT + k0 + c4);
            float4 ha = make_float4(hif(va.x), hif(va.y), hif(va.z), hif(va.w));
            float4 hb = make_float4(hif(vb.x), hif(vb.y), hif(vb.z), hif(vb.w));
            const int s = r * SROW + c4;
            *(float4*)(sAh + s) = ha;
            *(float4*)(sAl + s) = make_float4(va.x - ha.x, va.y - ha.y,
                                              va.z - ha.z, va.w - ha.w);
            *(float4*)(sBh + s) = hb;
            *(float4*)(sBl + s) = make_float4(vb.x - hb.x, vb.y - hb.y,
                                              vb.z - hb.z, vb.w - hb.w);
        }
        __syncthreads();

        #pragma unroll
        for (int kk = 0; kk < 32; kk += 8) {
            uint32_t af[4][4], bh[4][2], bl[4][2];
            #pragma unroll
            for (int t = 0; t < 4; t++) {
                const int rb = (wm * 64 + t * 16 + gid) * SROW + kk + tig;
                af[t][0] = fau(sAh[rb]);
                af[t][1] = fau(sAh[rb + 8 * SROW]);
                af[t][2] = fau(sAh[rb + 4]);
                af[t][3] = fau(sAh[rb + 8 * SROW + 4]);
            }
            #pragma unroll
            for (int u = 0; u < 4; u++) {
                const int rb = (wn * 32 + u * 8 + gid) * SROW + kk + tig;
                bh[u][0] = fau(sBh[rb]);
                bh[u][1] = fau(sBh[rb + 4]);
                bl[u][0] = fau(sBl[rb]);
                bl[u][1] = fau(sBl[rb + 4]);
            }
            #pragma unroll
            for (int t = 0; t < 4; t++)
                #pragma unroll
                for (int u = 0; u < 4; u++)
                    mma_tf32(acc[t][u], af[t], bh[u]);
            #pragma unroll
            for (int t = 0; t < 4; t++)
                #pragma unroll
                for (int u = 0; u < 4; u++)
                    mma_tf32(acc[t][u], af[t], bl[u]);
            #pragma unroll
            for (int t = 0; t < 4; t++) {
                const int rb = (wm * 64 + t * 16 + gid) * SROW + kk + tig;
                af[t][0] = fau(sAl[rb]);
                af[t][1] = fau(sAl[rb + 8 * SROW]);
                af[t][2] = fau(sAl[rb + 4]);
                af[t][3] = fau(sAl[rb + 8 * SROW + 4]);
            }
            #pragma unroll
            for (int t = 0; t < 4; t++)
                #pragma unroll
                for (int u = 0; u < 4; u++)
                    mma_tf32(acc[t][u], af[t], bh[u]);
        }
    }

    const int rbase = m0 + wm * 64;
    const int cbase = n0 + wn * 32;
    #pragma unroll
    for (int t = 0; t < 4; t++) {
        #pragma unroll
        for (int u = 0; u < 4; u++) {
            const int c = cbase + u * 8 + tig * 2;
            float b0 = 0.f, b1 = 0.f;
            if (bias) { b0 = bias[c]; b1 = bias[c + 1]; }
            const int r0 = rbase + t * 16 + gid;
            *(float2*)(C + (size_t)r0 * ldc + c) =
                make_float2(acc[t][u][0] + b0, acc[t][u][1] + b1);
            *(float2*)(C + (size_t)(r0 + 8) * ldc + c) =
                make_float2(acc[t][u][2] + b0, acc[t][u][3] + b1);
        }
    }
}

// ===========================================================================
// Pre-pass: V -> V^T [bh][dim][key] (unsplit, no permutation).
// ===========================================================================
__global__ __launch_bounds__(256) void prep_v() {
    __shared__ float sv[64][68];
    const int bh = blockIdx.y;
    const int kt = blockIdx.x;
    const int b = bh / HH, h = bh - b * HH;
    const int tid = threadIdx.x;
    #pragma unroll
    for (int p = 0; p < 4; p++) {
        const int j = tid + p * 256;
        const int key = j >> 4, c4 = (j & 15) * 4;
        float4 v = *(const float4*)(g_qkv +
            ((size_t)(b * NN + kt * 64 + key)) * E3 + h * 192 + 128 + c4);
        *(float4*)&sv[key][c4] = v;
    }
    __syncthreads();
    #pragma unroll
    for (int p = 0; p < 4; p++) {
        const int j = tid + p * 256;
        const int d = j >> 4, key4 = (j & 15) * 4;
        float4 o = make_float4(sv[key4 + 0][d], sv[key4 + 1][d],
                               sv[key4 + 2][d], sv[key4 + 3][d]);
        *(float4*)(g_vt + ((size_t)bh * 64 + d) * NN + kt * 64 + key4) = o;
    }
}

// ===========================================================================
// Flash attention, split-tf32 HMMA, high-occupancy version.
// CTA = 128 threads (4 warps), q-tile 64 (warp w owns rows 16w..16w+15).
// Q/K/V unsplit in smem (52 KB -> 4 CTAs/SM); hi/lo split in registers.
// P redistributed acc->A-fragment via quad shuffles (no smem).
// ===========================================================================
#define ASTR 68
#define ATILE (64 * ASTR)
#define ATTN_SMEM (3 * ATILE * 4)   // 52224 B

__global__ __launch_bounds__(128, 4) void attn_hmma() {
    extern __shared__ float sm[];
    float* sQ = sm;                 // [64 q][64 d]  (pre-scaled x8)
    float* sK = sQ + ATILE;         // [64 n][64 d]
    float* sV = sK + ATILE;         // [64 d][64 key]

    const int bh = blockIdx.y;
    const int q0 = blockIdx.x * 64;
    const int tid = threadIdx.x;
    const int wid = tid >> 5, lane = tid & 31;
    const int gid = lane >> 2, tig = lane & 3;
    const int b = bh / HH, h = bh - b * HH;
    const int r0 = wid * 16 + gid;
    const int qb = lane & ~3;            // quad base lane
    const int src0 = qb + (tig >> 1);
    const int src1 = src0 + 2;
    const int esel = tig & 1;

    // Stage Q (x8 folded here): 64 rows x 64 floats, 128 threads x 8 float4
    {
        const float* qg = g_qkv + ((size_t)(b * NN + q0)) * E3 + h * 192;
        #pragma unroll
        for (int p = 0; p < 8; p++) {
            const int j = tid + p * 128;
            const int r = j >> 4, c4 = (j & 15) * 4;
            float4 v = *(const float4*)(qg + (size_t)r * E3 + c4);
            *(float4*)&sQ[r * ASTR + c4] =
                make_float4(v.x * 8.f, v.y * 8.f, v.z * 8.f, v.w * 8.f);
        }
    }

    float oa[8][4] = {};
    float mrow0 = -1e30f, mrow1 = -1e30f, lrow0 = 0.f, lrow1 = 0.f;

    for (int kt = 0; kt < 16; kt++) {
        __syncthreads();   // protect sK/sV (and sQ on first iter)
        {
            const float* kg = g_qkv + ((size_t)(b * NN + kt * 64)) * E3 + h * 192 + 64;
            const float* vg = g_vt + ((size_t)bh * 64) * NN + kt * 64;
            #pragma unroll
            for (int p = 0; p < 8; p++) {
                const int j = tid + p * 128;
                const int r = j >> 4, c4 = (j & 15) * 4;
                *(float4*)&sK[r * ASTR + c4] = *(const float4*)(kg + (size_t)r * E3 + c4);
                *(float4*)&sV[r * ASTR + c4] = *(const float4*)(vg + (size_t)r * NN + c4);
            }
        }
        __syncthreads();

        // ---- S = Q K^T (3-pass split, fragments split in registers) ----
        float s[8][4] = {};
        #pragma unroll
        for (int kk = 0; kk < 64; kk += 8) {
            float a0 = sQ[r0 * ASTR + kk + tig];
            float a1 = sQ[(r0 + 8) * ASTR + kk + tig];
            float a2 = sQ[r0 * ASTR + kk + tig + 4];
            float a3 = sQ[(r0 + 8) * ASTR + kk + tig + 4];
            uint32_t ah[4] = {hi_bits(a0), hi_bits(a1), hi_bits(a2), hi_bits(a3)};
            uint32_t al[4] = {fau(a0 - __uint_as_float(ah[0])),
                              fau(a1 - __uint_as_float(ah[1])),
                              fau(a2 - __uint_as_float(ah[2])),
                              fau(a3 - __uint_as_float(ah[3]))};
            #pragma unroll
            for (int u = 0; u < 8; u++) {
                const int n = u * 8 + gid;
                float b0 = sK[n * ASTR + kk + tig];
                float b1 = sK[n * ASTR + kk + tig + 4];
                uint32_t bh[2] = {hi_bits(b0), hi_bits(b1)};
                uint32_t bl[2] = {fau(b0 - __uint_as_float(bh[0])),
                                  fau(b1 - __uint_as_float(bh[1]))};
                mma_tf32(s[u], ah, bh);
                mma_tf32(s[u], ah, bl);
                mma_tf32(s[u], al, bh);
            }
        }

        // ---- warp-local online softmax (rows r0, r0+8) ----
        float mt0 = -1e30f, mt1 = -1e30f;
        #pragma unroll
        for (int u = 0; u < 8; u++) {
            mt0 = fmaxf(mt0, fmaxf(s[u][0], s[u][1]));
            mt1 = fmaxf(mt1, fmaxf(s[u][2], s[u][3]));
        }
        #pragma unroll
        for (int off = 1; off < 4; off <<= 1) {
            mt0 = fmaxf(mt0, __shfl_xor_sync(0xffffffffu, mt0, off));
            mt1 = fmaxf(mt1, __shfl_xor_sync(0xffffffffu, mt1, off));
        }
        const float mn0 = fmaxf(mrow0, mt0);
        const float mn1 = fmaxf(mrow1, mt1);
        const float f0 = __expf(mrow0 - mn0);
        const float f1 = __expf(mrow1 - mn1);
        float ls0 = 0.f, ls1 = 0.f;
        #pragma unroll
        for (int u = 0; u < 8; u++) {
            s[u][0] = __expf(s[u][0] - mn0);
            s[u][1] = __expf(s[u][1] - mn0);
            s[u][2] = __expf(s[u][2] - mn1);
            s[u][3] = __expf(s[u][3] - mn1);
            ls0 += s[u][0] + s[u][1];
            ls1 += s[u][2] + s[u][3];
        }
        #pragma unroll
        for (int off = 1; off < 4; off <<= 1) {
            ls0 += __shfl_xor_sync(0xffffffffu, ls0, off);
            ls1 += __shfl_xor_sync(0xffffffffu, ls1, off);
        }
        lrow0 = lrow0 * f0 + ls0;  mrow0 = mn0;
        lrow1 = lrow1 * f1 + ls1;  mrow1 = mn1;

        #pragma unroll
        for (int u = 0; u < 8; u++) {
            oa[u][0] *= f0; oa[u][1] *= f0;
            oa[u][2] *= f1; oa[u][3] *= f1;
        }

        // ---- O += P V (P acc->A-frag via quad shuffles; 3-pass split) ----
        #pragma unroll
        for (int kk = 0; kk < 8; kk++) {     // key group kk = u-tile kk of s
            // A-frag: a0=P[g][tig], a1=P[g+8][tig], a2=P[g][tig+4], a3=P[g+8][tig+4]
            float v00 = __shfl_sync(0xffffffffu, s[kk][0], src0);
            float v01 = __shfl_sync(0xffffffffu, s[kk][1], src0);
            float v10 = __shfl_sync(0xffffffffu, s[kk][2], src0);
            float v11 = __shfl_sync(0xffffffffu, s[kk][3], src0);
            float w00 = __shfl_sync(0xffffffffu, s[kk][0], src1);
            float w01 = __shfl_sync(0xffffffffu, s[kk][1], src1);
            float w10 = __shfl_sync(0xffffffffu, s[kk][2], src1);
            float w11 = __shfl_sync(0xffffffffu, s[kk][3], src1);
            float a0 = esel ? v01 : v00;
            float a1 = esel ? v11 : v10;
            float a2 = esel ? w01 : w00;
            float a3 = esel ? w11 : w10;
            uint32_t ah[4] = {hi_bits(a0), hi_bits(a1), hi_bits(a2), hi_bits(a3)};
            uint32_t al[4] = {fau(a0 - __uint_as_float(ah[0])),
                              fau(a1 - __uint_as_float(ah[1])),
                              fau(a2 - __uint_as_float(ah[2])),
                              fau(a3 - __uint_as_float(ah[3]))};
            #pragma unroll
            for (int u = 0; u < 8; u++) {     // u = output dim tile
                const int n = u * 8 + gid;
                float b0 = sV[n * ASTR + kk * 8 + tig];
                float b1 = sV[n * ASTR + kk * 8 + tig + 4];
                uint32_t bh[2] = {hi_bits(b0), hi_bits(b1)};
                uint32_t bl[2] = {fau(b0 - __uint_as_float(bh[0])),
                                  fau(b1 - __uint_as_float(bh[1]))};
                mma_tf32(oa[u], ah, bh);
                mma_tf32(oa[u], ah, bl);
                mma_tf32(oa[u], al, bh);
            }
        }
    }

    // Epilogue
    const float il0 = 1.f / lrow0;
    const float il1 = 1.f / lrow1;
    #pragma unroll
    for (int u = 0; u < 8; u++) {
        const int col = h * 64 + u * 8 + 2 * tig;
        *(float2*)&g_o[((size_t)(b * NN + q0 + r0)) * DH + col] =
            make_float2(oa[u][0] * il0, oa[u][1] * il0);
        *(float2*)&g_o[((size_t)(b * NN + q0 + r0 + 8)) * DH + col] =
            make_float2(oa[u][2] * il1, oa[u][3] * il1);
    }
}

// ===========================================================================
extern "C" void kernel_launch(void* const* d_in, const int* in_sizes, int n_in,
                              void* d_out, int out_size) {
    const float* img  = (const float*)d_in[0];   // [8,1024,768]
    const float* Wqkv = (const float*)d_in[1];   // [2304,768]
    const float* Wfc  = (const float*)d_in[2];   // [768,768]
    const float* bfc  = (const float*)d_in[3];   // [768]
    float* out = (float*)d_out;                  // [8,1024,768]

    void* qkvp = nullptr;
    void* op = nullptr;
    cudaGetSymbolAddress(&qkvp, g_qkv);
    cudaGetSymbolAddress(&op, g_o);

    cudaFuncSetAttribute(mm_hmma, cudaFuncAttributeMaxDynamicSharedMemorySize,
                         SMEM_MM);
    cudaFuncSetAttribute(attn_hmma, cudaFuncAttributeMaxDynamicSharedMemorySize,
                         ATTN_SMEM);

    // 1) QKV projection: [8192,2304] = img @ Wqkv^T
    mm_hmma<<<dim3(E3 / 128, NTOK / 128), 256, SMEM_MM>>>(img, Wqkv, nullptr,
                                                          (float*)qkvp, E3);

    // 2) V transpose
    prep_v<<<dim3(16, NBH), 256>>>();

    // 3) Flash attention (split-tf32 HMMA, 4 CTA/SM)
    attn_hmma<<<dim3(NN / 64, NBH), 128, ATTN_SMEM>>>();

    // 4) Output projection + bias
    mm_hmma<<<dim3(DIM / 128, NTOK / 128), 256, SMEM_MM>>>((const float*)op, Wfc,
                                                           bfc, out, DIM);
}

// round 8
// speedup vs baseline: 1.8209x; 1.3523x over previous
#include <cuda_runtime.h>
#include <cstdint>
#include <math.h>

#define BB 8
#define NN 1024
#define HH 12
#define DHD 64
#define DIM 768
#define DH  768
#define E3  2304
#define NTOK (BB*NN)
#define KTOT 768
#define NBH (BB*HH)   // 96

// Scratch (device globals; no runtime allocation allowed)
__device__ float g_qkv[(size_t)NTOK * E3];
__device__ float g_o[(size_t)NTOK * DH];
__device__ float g_vt[(size_t)NBH * DHD * NN];   // [bh][dim][key]

__device__ __forceinline__ uint32_t hi_bits(float x) {
    return __float_as_uint(x) & 0xFFFFE000u;
}
__device__ __forceinline__ uint32_t fau(float x) { return __float_as_uint(x); }

__device__ __forceinline__ void mma_tf32(float* d, const uint32_t* a,
                                         const uint32_t* b) {
    asm volatile(
        "mma.sync.aligned.m16n8k8.row.col.f32.tf32.tf32.f32 "
        "{%0,%1,%2,%3}, {%4,%5,%6,%7}, {%8,%9}, {%0,%1,%2,%3};"
        : "+f"(d[0]), "+f"(d[1]), "+f"(d[2]), "+f"(d[3])
        : "r"(a[0]), "r"(a[1]), "r"(a[2]), "r"(a[3]), "r"(b[0]), "r"(b[1]));
}

__device__ __forceinline__ uint32_t smem_u32(const void* p) {
    uint32_t a;
    asm("{ .reg .u64 t; cvta.to.shared.u64 t, %1; cvt.u32.u64 %0, t; }"
        : "=r"(a) : "l"(p));
    return a;
}
__device__ __forceinline__ void cp_async16(uint32_t dst, const void* src) {
    asm volatile("cp.async.cg.shared.global [%0], [%1], 16;"
                 :: "r"(dst), "l"(src));
}
#define CP_COMMIT() asm volatile("cp.async.commit_group;" ::: "memory")
#define CP_WAIT1()  asm volatile("cp.async.wait_group 1;" ::: "memory")

// ===========================================================================
// Split-tf32 GEMM: raw A/B in smem (cp.async double-buffered), hi/lo split
// in registers at fragment load. 128x128 tile, 8 warps, K-chunk 32.
// ===========================================================================
#define SROW 36                          // 144 B row stride (16B-aligned)
#define SMAT (128 * SROW)                // floats per matrix per stage
#define SMEM_MM (4 * SMAT * 4)           // 2 stages x (A + B) = 72 KB

__global__ __launch_bounds__(256, 2) void mm_hmma(const float* __restrict__ A,
                                                  const float* __restrict__ Bm,
                                                  const float* __restrict__ bias,
                                                  float* __restrict__ C, int ldc) {
    extern __shared__ float smem[];
    const uint32_t sb = smem_u32(smem);

    const int tid = threadIdx.x;
    const int wid = tid >> 5, lane = tid & 31;
    const int gid = lane >> 2, tig = lane & 3;
    const int wm = wid & 1;
    const int wn = wid >> 1;
    const int m0 = blockIdx.y * 128;
    const int n0 = blockIdx.x * 128;

    // cp.async staging coords: 2 threads per row; each thread loads 4 x 16B
    // per matrix (slots scol..scol+3), covering all 8 float4 slots per row.
    const int srow = tid >> 1;                 // 0..127
    const int scol = (tid & 1) * 4;            // slot base 0 or 4

    float acc[4][4][4] = {};

    // Prologue: stage chunks 0 and 1
    #pragma unroll
    for (int st = 0; st < 2; st++) {
        const int k0 = st * 32;
        const uint32_t bufA = sb + (2 * st) * SMAT * 4;
        const uint32_t bufB = sb + (2 * st + 1) * SMAT * 4;
        #pragma unroll
        for (int p = 0; p < 4; p++) {
            const int c4 = scol + p;           // float4 slot 0..7
            cp_async16(bufA + (srow * SROW + c4 * 4) * 4,
                       A + (size_t)(m0 + srow) * KTOT + k0 + c4 * 4);
            cp_async16(bufB + (srow * SROW + c4 * 4) * 4,
                       Bm + (size_t)(n0 + srow) * KTOT + k0 + c4 * 4);
        }
        CP_COMMIT();
    }

    const int NCH = KTOT / 32;                 // 24
    for (int ch = 0; ch < NCH; ch++) {
        CP_WAIT1();
        __syncthreads();
        const int buf = ch & 1;
        const float* sA = smem + (2 * buf) * SMAT;
        const float* sB = smem + (2 * buf + 1) * SMAT;

        #pragma unroll
        for (int kk = 0; kk < 32; kk += 8) {
            // B fragments: raw loads, split in regs (live across t loop)
            uint32_t bh[4][2], bl[4][2];
            #pragma unroll
            for (int u = 0; u < 4; u++) {
                const int rb = (wn * 32 + u * 8 + gid) * SROW + kk + tig;
                float b0 = sB[rb], b1 = sB[rb + 4];
                bh[u][0] = hi_bits(b0);
                bh[u][1] = hi_bits(b1);
                bl[u][0] = fau(b0 - __uint_as_float(bh[u][0]));
                bl[u][1] = fau(b1 - __uint_as_float(bh[u][1]));
            }
            #pragma unroll
            for (int t = 0; t < 4; t++) {
                const int rb = (wm * 64 + t * 16 + gid) * SROW + kk + tig;
                float a0 = sA[rb];
                float a1 = sA[rb + 8 * SROW];
                float a2 = sA[rb + 4];
                float a3 = sA[rb + 8 * SROW + 4];
                uint32_t ah[4] = {hi_bits(a0), hi_bits(a1),
                                  hi_bits(a2), hi_bits(a3)};
                uint32_t al[4] = {fau(a0 - __uint_as_float(ah[0])),
                                  fau(a1 - __uint_as_float(ah[1])),
                                  fau(a2 - __uint_as_float(ah[2])),
                                  fau(a3 - __uint_as_float(ah[3]))};
                #pragma unroll
                for (int u = 0; u < 4; u++) {
                    mma_tf32(acc[t][u], ah, bh[u]);
                    mma_tf32(acc[t][u], ah, bl[u]);
                    mma_tf32(acc[t][u], al, bh[u]);
                }
            }
        }
        __syncthreads();
        // Stage chunk ch+2 into the buffer just freed
        if (ch + 2 < NCH) {
            const int k0 = (ch + 2) * 32;
            const uint32_t bufA = sb + (2 * buf) * SMAT * 4;
            const uint32_t bufB = sb + (2 * buf + 1) * SMAT * 4;
            #pragma unroll
            for (int p = 0; p < 4; p++) {
                const int c4 = scol + p;
                cp_async16(bufA + (srow * SROW + c4 * 4) * 4,
                           A + (size_t)(m0 + srow) * KTOT + k0 + c4 * 4);
                cp_async16(bufB + (srow * SROW + c4 * 4) * 4,
                           Bm + (size_t)(n0 + srow) * KTOT + k0 + c4 * 4);
            }
        }
        CP_COMMIT();   // commit every iter (possibly empty) to keep wait ordering
    }

    const int rbase = m0 + wm * 64;
    const int cbase = n0 + wn * 32;
    #pragma unroll
    for (int t = 0; t < 4; t++) {
        #pragma unroll
        for (int u = 0; u < 4; u++) {
            const int c = cbase + u * 8 + tig * 2;
            float b0 = 0.f, b1 = 0.f;
            if (bias) { b0 = bias[c]; b1 = bias[c + 1]; }
            const int r0 = rbase + t * 16 + gid;
            *(float2*)(C + (size_t)r0 * ldc + c) =
                make_float2(acc[t][u][0] + b0, acc[t][u][1] + b1);
            *(float2*)(C + (size_t)(r0 + 8) * ldc + c) =
                make_float2(acc[t][u][2] + b0, acc[t][u][3] + b1);
        }
    }
}

// ===========================================================================
// Pre-pass: V -> V^T [bh][dim][key].
// ===========================================================================
__global__ __launch_bounds__(256) void prep_v() {
    __shared__ float sv[64][68];
    const int bh = blockIdx.y;
    const int kt = blockIdx.x;
    const int b = bh / HH, h = bh - b * HH;
    const int tid = threadIdx.x;
    #pragma unroll
    for (int p = 0; p < 4; p++) {
        const int j = tid + p * 256;
        const int key = j >> 4, c4 = (j & 15) * 4;
        float4 v = *(const float4*)(g_qkv +
            ((size_t)(b * NN + kt * 64 + key)) * E3 + h * 192 + 128 + c4);
        *(float4*)&sv[key][c4] = v;
    }
    __syncthreads();
    #pragma unroll
    for (int p = 0; p < 4; p++) {
        const int j = tid + p * 256;
        const int d = j >> 4, key4 = (j & 15) * 4;
        float4 o = make_float4(sv[key4 + 0][d], sv[key4 + 1][d],
                               sv[key4 + 2][d], sv[key4 + 3][d]);
        *(float4*)(g_vt + ((size_t)bh * 64 + d) * NN + kt * 64 + key4) = o;
    }
}

// ===========================================================================
// Flash attention, split-tf32 HMMA (unchanged — proven).
// ===========================================================================
#define ASTR 68
#define ATILE (64 * ASTR)
#define ATTN_SMEM (3 * ATILE * 4)   // 52224 B

__global__ __launch_bounds__(128, 4) void attn_hmma() {
    extern __shared__ float sm[];
    float* sQ = sm;
    float* sK = sQ + ATILE;
    float* sV = sK + ATILE;

    const int bh = blockIdx.y;
    const int q0 = blockIdx.x * 64;
    const int tid = threadIdx.x;
    const int wid = tid >> 5, lane = tid & 31;
    const int gid = lane >> 2, tig = lane & 3;
    const int b = bh / HH, h = bh - b * HH;
    const int r0 = wid * 16 + gid;
    const int qb = lane & ~3;
    const int src0 = qb + (tig >> 1);
    const int src1 = src0 + 2;
    const int esel = tig & 1;

    {
        const float* qg = g_qkv + ((size_t)(b * NN + q0)) * E3 + h * 192;
        #pragma unroll
        for (int p = 0; p < 8; p++) {
            const int j = tid + p * 128;
            const int r = j >> 4, c4 = (j & 15) * 4;
            float4 v = *(const float4*)(qg + (size_t)r * E3 + c4);
            *(float4*)&sQ[r * ASTR + c4] =
                make_float4(v.x * 8.f, v.y * 8.f, v.z * 8.f, v.w * 8.f);
        }
    }

    float oa[8][4] = {};
    float mrow0 = -1e30f, mrow1 = -1e30f, lrow0 = 0.f, lrow1 = 0.f;

    for (int kt = 0; kt < 16; kt++) {
        __syncthreads();
        {
            const float* kg = g_qkv + ((size_t)(b * NN + kt * 64)) * E3 + h * 192 + 64;
            const float* vg = g_vt + ((size_t)bh * 64) * NN + kt * 64;
            #pragma unroll
            for (int p = 0; p < 8; p++) {
                const int j = tid + p * 128;
                const int r = j >> 4, c4 = (j & 15) * 4;
                *(float4*)&sK[r * ASTR + c4] = *(const float4*)(kg + (size_t)r * E3 + c4);
                *(float4*)&sV[r * ASTR + c4] = *(const float4*)(vg + (size_t)r * NN + c4);
            }
        }
        __syncthreads();

        float s[8][4] = {};
        #pragma unroll
        for (int kk = 0; kk < 64; kk += 8) {
            float a0 = sQ[r0 * ASTR + kk + tig];
            float a1 = sQ[(r0 + 8) * ASTR + kk + tig];
            float a2 = sQ[r0 * ASTR + kk + tig + 4];
            float a3 = sQ[(r0 + 8) * ASTR + kk + tig + 4];
            uint32_t ah[4] = {hi_bits(a0), hi_bits(a1), hi_bits(a2), hi_bits(a3)};
            uint32_t al[4] = {fau(a0 - __uint_as_float(ah[0])),
                              fau(a1 - __uint_as_float(ah[1])),
                              fau(a2 - __uint_as_float(ah[2])),
                              fau(a3 - __uint_as_float(ah[3]))};
            #pragma unroll
            for (int u = 0; u < 8; u++) {
                const int n = u * 8 + gid;
                float b0 = sK[n * ASTR + kk + tig];
                float b1 = sK[n * ASTR + kk + tig + 4];
                uint32_t bh[2] = {hi_bits(b0), hi_bits(b1)};
                uint32_t bl[2] = {fau(b0 - __uint_as_float(bh[0])),
                                  fau(b1 - __uint_as_float(bh[1]))};
                mma_tf32(s[u], ah, bh);
                mma_tf32(s[u], ah, bl);
                mma_tf32(s[u], al, bh);
            }
        }

        float mt0 = -1e30f, mt1 = -1e30f;
        #pragma unroll
        for (int u = 0; u < 8; u++) {
            mt0 = fmaxf(mt0, fmaxf(s[u][0], s[u][1]));
            mt1 = fmaxf(mt1, fmaxf(s[u][2], s[u][3]));
        }
        #pragma unroll
        for (int off = 1; off < 4; off <<= 1) {
            mt0 = fmaxf(mt0, __shfl_xor_sync(0xffffffffu, mt0, off));
            mt1 = fmaxf(mt1, __shfl_xor_sync(0xffffffffu, mt1, off));
        }
        const float mn0 = fmaxf(mrow0, mt0);
        const float mn1 = fmaxf(mrow1, mt1);
        const float f0 = __expf(mrow0 - mn0);
        const float f1 = __expf(mrow1 - mn1);
        float ls0 = 0.f, ls1 = 0.f;
        #pragma unroll
        for (int u = 0; u < 8; u++) {
            s[u][0] = __expf(s[u][0] - mn0);
            s[u][1] = __expf(s[u][1] - mn0);
            s[u][2] = __expf(s[u][2] - mn1);
            s[u][3] = __expf(s[u][3] - mn1);
            ls0 += s[u][0] + s[u][1];
            ls1 += s[u][2] + s[u][3];
        }
        #pragma unroll
        for (int off = 1; off < 4; off <<= 1) {
            ls0 += __shfl_xor_sync(0xffffffffu, ls0, off);
            ls1 += __shfl_xor_sync(0xffffffffu, ls1, off);
        }
        lrow0 = lrow0 * f0 + ls0;  mrow0 = mn0;
        lrow1 = lrow1 * f1 + ls1;  mrow1 = mn1;

        #pragma unroll
        for (int u = 0; u < 8; u++) {
            oa[u][0] *= f0; oa[u][1] *= f0;
            oa[u][2] *= f1; oa[u][3] *= f1;
        }

        #pragma unroll
        for (int kk = 0; kk < 8; kk++) {
            float v00 = __shfl_sync(0xffffffffu, s[kk][0], src0);
            float v01 = __shfl_sync(0xffffffffu, s[kk][1], src0);
            float v10 = __shfl_sync(0xffffffffu, s[kk][2], src0);
            float v11 = __shfl_sync(0xffffffffu, s[kk][3], src0);
            float w00 = __shfl_sync(0xffffffffu, s[kk][0], src1);
            float w01 = __shfl_sync(0xffffffffu, s[kk][1], src1);
            float w10 = __shfl_sync(0xffffffffu, s[kk][2], src1);
            float w11 = __shfl_sync(0xffffffffu, s[kk][3], src1);
            float a0 = esel ? v01 : v00;
            float a1 = esel ? v11 : v10;
            float a2 = esel ? w01 : w00;
            float a3 = esel ? w11 : w10;
            uint32_t ah[4] = {hi_bits(a0), hi_bits(a1), hi_bits(a2), hi_bits(a3)};
            uint32_t al[4] = {fau(a0 - __uint_as_float(ah[0])),
                              fau(a1 - __uint_as_float(ah[1])),
                              fau(a2 - __uint_as_float(ah[2])),
                              fau(a3 - __uint_as_float(ah[3]))};
            #pragma unroll
            for (int u = 0; u < 8; u++) {
                const int n = u * 8 + gid;
                float b0 = sV[n * ASTR + kk * 8 + tig];
                float b1 = sV[n * ASTR + kk * 8 + tig + 4];
                uint32_t bh[2] = {hi_bits(b0), hi_bits(b1)};
                uint32_t bl[2] = {fau(b0 - __uint_as_float(bh[0])),
                                  fau(b1 - __uint_as_float(bh[1]))};
                mma_tf32(oa[u], ah, bh);
                mma_tf32(oa[u], ah, bl);
                mma_tf32(oa[u], al, bh);
            }
        }
    }

    const float il0 = 1.f / lrow0;
    const float il1 = 1.f / lrow1;
    #pragma unroll
    for (int u = 0; u < 8; u++) {
        const int col = h * 64 + u * 8 + 2 * tig;
        *(float2*)&g_o[((size_t)(b * NN + q0 + r0)) * DH + col] =
            make_float2(oa[u][0] * il0, oa[u][1] * il0);
        *(float2*)&g_o[((size_t)(b * NN + q0 + r0 + 8)) * DH + col] =
            make_float2(oa[u][2] * il1, oa[u][3] * il1);
    }
}

// ===========================================================================
extern "C" void kernel_launch(void* const* d_in, const int* in_sizes, int n_in,
                              void* d_out, int out_size) {
    const float* img  = (const float*)d_in[0];   // [8,1024,768]
    const float* Wqkv = (const float*)d_in[1];   // [2304,768]
    const float* Wfc  = (const float*)d_in[2];   // [768,768]
    const float* bfc  = (const float*)d_in[3];   // [768]
    float* out = (float*)d_out;                  // [8,1024,768]

    void* qkvp = nullptr;
    void* op = nullptr;
    cudaGetSymbolAddress(&qkvp, g_qkv);
    cudaGetSymbolAddress(&op, g_o);

    cudaFuncSetAttribute(mm_hmma, cudaFuncAttributeMaxDynamicSharedMemorySize,
                         SMEM_MM);
    cudaFuncSetAttribute(attn_hmma, cudaFuncAttributeMaxDynamicSharedMemorySize,
                         ATTN_SMEM);

    // 1) QKV projection
    mm_hmma<<<dim3(E3 / 128, NTOK / 128), 256, SMEM_MM>>>(img, Wqkv, nullptr,
                                                          (float*)qkvp, E3);
    // 2) V transpose
    prep_v<<<dim3(16, NBH), 256>>>();
    // 3) Flash attention
    attn_hmma<<<dim3(NN / 64, NBH), 128, ATTN_SMEM>>>();
    // 4) Output projection + bias
    mm_hmma<<<dim3(DIM / 128, NTOK / 128), 256, SMEM_MM>>>((const float*)op, Wfc,
                                                           bfc, out, DIM);
}